// round 2
// baseline (speedup 1.0000x reference)
#include <cuda_runtime.h>
#include <cuda_bf16.h>

// DiffJPEG: per-8x8-block  D @ X @ D^T  -> round(./Q)*Q -> D^T @ M @ D
// One thread per 8x8 block. All DCT/Q coefficients are compile-time float
// literals so ptxas emits FFMA with immediate multiplier (rt_SMSP=1).

// D[i][j] = c_i * cos((2j+1) i pi / 16), c_0 = sqrt(1/8), c_i = 0.5 otherwise.
__device__ constexpr float DM[8][8] = {
    { 0.3535533905932738f,  0.3535533905932738f,  0.3535533905932738f,  0.3535533905932738f,
      0.3535533905932738f,  0.3535533905932738f,  0.3535533905932738f,  0.3535533905932738f },
    { 0.4903926402016152f,  0.4157348061512726f,  0.2777851165098011f,  0.0975451610080642f,
     -0.0975451610080642f, -0.2777851165098011f, -0.4157348061512726f, -0.4903926402016152f },
    { 0.4619397662556434f,  0.1913417161825449f, -0.1913417161825449f, -0.4619397662556434f,
     -0.4619397662556434f, -0.1913417161825449f,  0.1913417161825449f,  0.4619397662556434f },
    { 0.4157348061512726f, -0.0975451610080642f, -0.4903926402016152f, -0.2777851165098011f,
      0.2777851165098011f,  0.4903926402016152f,  0.0975451610080642f, -0.4157348061512726f },
    { 0.3535533905932738f, -0.3535533905932738f, -0.3535533905932738f,  0.3535533905932738f,
      0.3535533905932738f, -0.3535533905932738f, -0.3535533905932738f,  0.3535533905932738f },
    { 0.2777851165098011f, -0.4903926402016152f,  0.0975451610080642f,  0.4157348061512726f,
     -0.4157348061512726f, -0.0975451610080642f,  0.4903926402016152f, -0.2777851165098011f },
    { 0.1913417161825449f, -0.4619397662556434f,  0.4619397662556434f, -0.1913417161825449f,
     -0.1913417161825449f,  0.4619397662556434f, -0.4619397662556434f,  0.1913417161825449f },
    { 0.0975451610080642f, -0.2777851165098011f,  0.4157348061512726f, -0.4903926402016152f,
      0.4903926402016152f, -0.4157348061512726f,  0.2777851165098011f, -0.0975451610080642f },
};

// quality=50: floor((q*100+50)/100) = q for integer q, so Q == q_luma.
__device__ constexpr float QM[8][8] = {
    { 16.f, 11.f, 10.f, 16.f,  24.f,  40.f,  51.f,  61.f },
    { 12.f, 12.f, 14.f, 19.f,  26.f,  58.f,  60.f,  55.f },
    { 14.f, 13.f, 16.f, 24.f,  40.f,  57.f,  69.f,  56.f },
    { 14.f, 17.f, 22.f, 29.f,  51.f,  87.f,  80.f,  62.f },
    { 18.f, 22.f, 37.f, 56.f,  68.f, 109.f, 103.f,  77.f },
    { 24.f, 35.f, 55.f, 64.f,  81.f, 104.f, 113.f,  92.f },
    { 49.f, 64.f, 78.f, 87.f, 103.f, 121.f, 120.f, 101.f },
    { 72.f, 92.f, 95.f, 98.f, 112.f, 100.f, 103.f,  99.f },
};

constexpr int W_IMG = 512;   // image width in floats (row stride)
constexpr int BW    = 64;    // blocks per row   (512/8)
constexpr int BH    = 64;    // block rows       (512/8)

__global__ void __launch_bounds__(256, 2)
diffjpeg_kernel(const float* __restrict__ in, float* __restrict__ out, int nblk)
{
    int tid = blockIdx.x * 256 + threadIdx.x;
    if (tid >= nblk) return;

    int bw  = tid & (BW - 1);          // block col
    int t1  = tid >> 6;
    int bh  = t1 & (BH - 1);           // block row
    int img = t1 >> 6;                 // fused (B,C) plane index

    size_t base = ((size_t)img << 18) + ((size_t)bh << 12) + ((size_t)bw << 3);
    const float* p = in  + base;
    float*       q = out + base;

    float T[8][8];

    // ---- T = D @ X : accumulate as rows of X stream in -------------------
    #pragma unroll
    for (int k = 0; k < 8; ++k) {
        float4 a = *reinterpret_cast<const float4*>(p + (size_t)k * W_IMG);
        float4 b = *reinterpret_cast<const float4*>(p + (size_t)k * W_IMG + 4);
        float x[8] = { a.x, a.y, a.z, a.w, b.x, b.y, b.z, b.w };
        #pragma unroll
        for (int i = 0; i < 8; ++i) {
            #pragma unroll
            for (int j = 0; j < 8; ++j) {
                if (k == 0) T[i][j]  = DM[i][0] * x[j];
                else        T[i][j] += DM[i][k] * x[j];
            }
        }
    }

    // ---- dct = T @ D^T, then quant/dequant, in place per row -------------
    #pragma unroll
    for (int i = 0; i < 8; ++i) {
        float r[8];
        #pragma unroll
        for (int j = 0; j < 8; ++j) {
            float s = T[i][0] * DM[j][0];
            #pragma unroll
            for (int k = 1; k < 8; ++k) s += T[i][k] * DM[j][k];
            // scaled = dct/Q ; forward value of STE quantize = round(scaled)
            float qv = rintf(s * (1.0f / QM[i][j]));   // round-half-even == jnp.round
            r[j] = qv * QM[i][j];
        }
        #pragma unroll
        for (int j = 0; j < 8; ++j) T[i][j] = r[j];
    }

    // ---- W = M @ D, in place per row --------------------------------------
    #pragma unroll
    for (int i = 0; i < 8; ++i) {
        float r[8];
        #pragma unroll
        for (int j = 0; j < 8; ++j) {
            float s = T[i][0] * DM[0][j];
            #pragma unroll
            for (int k = 1; k < 8; ++k) s += T[i][k] * DM[k][j];
            r[j] = s;
        }
        #pragma unroll
        for (int j = 0; j < 8; ++j) T[i][j] = r[j];
    }

    // ---- out = D^T @ W : produce one output row at a time, store it ------
    #pragma unroll
    for (int i = 0; i < 8; ++i) {
        float r[8];
        #pragma unroll
        for (int j = 0; j < 8; ++j) {
            float s = DM[0][i] * T[0][j];
            #pragma unroll
            for (int k = 1; k < 8; ++k) s += DM[k][i] * T[k][j];
            r[j] = s;
        }
        *reinterpret_cast<float4*>(q + (size_t)i * W_IMG)     = make_float4(r[0], r[1], r[2], r[3]);
        *reinterpret_cast<float4*>(q + (size_t)i * W_IMG + 4) = make_float4(r[4], r[5], r[6], r[7]);
    }
}

extern "C" void kernel_launch(void* const* d_in, const int* in_sizes, int n_in,
                              void* d_out, int out_size)
{
    const float* in  = (const float*)d_in[0];
    float*       out = (float*)d_out;
    int nblk = in_sizes[0] / 64;                 // number of 8x8 blocks
    int grid = (nblk + 255) / 256;
    diffjpeg_kernel<<<grid, 256>>>(in, out, nblk);
}

// round 3
// speedup vs baseline: 1.2685x; 1.2685x over previous
#include <cuda_runtime.h>
#include <cuda_bf16.h>

// DiffJPEG per-8x8-block: D @ X @ D^T -> round(./Q)*Q -> D^T @ M @ D
// One thread per block. All matmuls use packed fma.rn.f32x2 (FFMA2) so each
// fma-pipe issue retires 2 MACs. No transposes: column passes keep j-packed
// pairs; row passes broadcast scalar data against packed coefficient pairs.

using u64 = unsigned long long;

// D[i][j] = c_i * cos((2j+1) i pi / 16), c_0 = sqrt(1/8), else 0.5
__device__ constexpr float DMc[8][8] = {
    { 0.3535533905932738f,  0.3535533905932738f,  0.3535533905932738f,  0.3535533905932738f,
      0.3535533905932738f,  0.3535533905932738f,  0.3535533905932738f,  0.3535533905932738f },
    { 0.4903926402016152f,  0.4157348061512726f,  0.2777851165098011f,  0.0975451610080642f,
     -0.0975451610080642f, -0.2777851165098011f, -0.4157348061512726f, -0.4903926402016152f },
    { 0.4619397662556434f,  0.1913417161825449f, -0.1913417161825449f, -0.4619397662556434f,
     -0.4619397662556434f, -0.1913417161825449f,  0.1913417161825449f,  0.4619397662556434f },
    { 0.4157348061512726f, -0.0975451610080642f, -0.4903926402016152f, -0.2777851165098011f,
      0.2777851165098011f,  0.4903926402016152f,  0.0975451610080642f, -0.4157348061512726f },
    { 0.3535533905932738f, -0.3535533905932738f, -0.3535533905932738f,  0.3535533905932738f,
      0.3535533905932738f, -0.3535533905932738f, -0.3535533905932738f,  0.3535533905932738f },
    { 0.2777851165098011f, -0.4903926402016152f,  0.0975451610080642f,  0.4157348061512726f,
     -0.4157348061512726f, -0.0975451610080642f,  0.4903926402016152f, -0.2777851165098011f },
    { 0.1913417161825449f, -0.4619397662556434f,  0.4619397662556434f, -0.1913417161825449f,
     -0.1913417161825449f,  0.4619397662556434f, -0.4619397662556434f,  0.1913417161825449f },
    { 0.0975451610080642f, -0.2777851165098011f,  0.4157348061512726f, -0.4903926402016152f,
      0.4903926402016152f, -0.4157348061512726f,  0.2777851165098011f, -0.0975451610080642f },
};

// quality=50 -> Q == q_luma exactly.
__device__ constexpr float QMc[8][8] = {
    { 16.f, 11.f, 10.f, 16.f,  24.f,  40.f,  51.f,  61.f },
    { 12.f, 12.f, 14.f, 19.f,  26.f,  58.f,  60.f,  55.f },
    { 14.f, 13.f, 16.f, 24.f,  40.f,  57.f,  69.f,  56.f },
    { 14.f, 17.f, 22.f, 29.f,  51.f,  87.f,  80.f,  62.f },
    { 18.f, 22.f, 37.f, 56.f,  68.f, 109.f, 103.f,  77.f },
    { 24.f, 35.f, 55.f, 64.f,  81.f, 104.f, 113.f,  92.f },
    { 49.f, 64.f, 78.f, 87.f, 103.f, 121.f, 120.f, 101.f },
    { 72.f, 92.f, 95.f, 98.f, 112.f, 100.f, 103.f,  99.f },
};

__device__ __forceinline__ u64 pk(float a, float b) {
    return (u64)__float_as_uint(a) | ((u64)__float_as_uint(b) << 32);
}
__device__ __forceinline__ float lo2(u64 v) { return __uint_as_float((unsigned)v); }
__device__ __forceinline__ float hi2(u64 v) { return __uint_as_float((unsigned)(v >> 32)); }
__device__ __forceinline__ u64 fma2(u64 a, u64 b, u64 c) {
    u64 d; asm("fma.rn.f32x2 %0, %1, %2, %3;" : "=l"(d) : "l"(a), "l"(b), "l"(c)); return d;
}
__device__ __forceinline__ u64 mul2(u64 a, u64 b) {
    u64 d; asm("mul.rn.f32x2 %0, %1, %2;" : "=l"(d) : "l"(a), "l"(b)); return d;
}

__global__ void __launch_bounds__(256, 2)
diffjpeg_kernel(const float* __restrict__ in, float* __restrict__ out, int nblk)
{
    int tid = blockIdx.x * 256 + threadIdx.x;
    if (tid >= nblk) return;

    int bw  = tid & 63;           // block col (64 per row)
    int t1  = tid >> 6;
    int bh  = t1 & 63;            // block row
    int img = t1 >> 6;            // fused (B,C) plane

    size_t base = ((size_t)img << 18) + ((size_t)bh << 12) + ((size_t)bw << 3);
    const float* p = in  + base;
    float*       q = out + base;

    u64 A[8][4];   // 8 rows x 4 packed j-pairs

    // ---- pass 1: A = D @ X (column transform), streaming rows of X -------
    #pragma unroll
    for (int k = 0; k < 8; ++k) {
        const ulonglong2* rp = reinterpret_cast<const ulonglong2*>(p + (size_t)k * 512);
        ulonglong2 xa = rp[0];
        ulonglong2 xb = rp[1];
        u64 x0 = xa.x, x1 = xa.y, x2 = xb.x, x3 = xb.y;
        #pragma unroll
        for (int i = 0; i < 8; ++i) {
            u64 c = pk(DMc[i][k], DMc[i][k]);
            if (k == 0) {
                A[i][0] = mul2(c, x0); A[i][1] = mul2(c, x1);
                A[i][2] = mul2(c, x2); A[i][3] = mul2(c, x3);
            } else {
                A[i][0] = fma2(c, x0, A[i][0]); A[i][1] = fma2(c, x1, A[i][1]);
                A[i][2] = fma2(c, x2, A[i][2]); A[i][3] = fma2(c, x3, A[i][3]);
            }
        }
    }

    // ---- per row i: row-fwd (@ D^T), quantize, row-inv (@ D), in place ----
    #pragma unroll
    for (int i = 0; i < 8; ++i) {
        // unpack row i scalars (register-half access, free)
        float a[8];
        #pragma unroll
        for (int b = 0; b < 4; ++b) { a[2*b] = lo2(A[i][b]); a[2*b+1] = hi2(A[i][b]); }

        // row fwd: dct[l] = sum_j a[j] * D[l][j], packed over l-pairs
        u64 r[4];
        #pragma unroll
        for (int j = 0; j < 8; ++j) {
            u64 bs = pk(a[j], a[j]);
            #pragma unroll
            for (int l2 = 0; l2 < 4; ++l2) {
                u64 c = pk(DMc[2*l2][j], DMc[2*l2+1][j]);
                r[l2] = (j == 0) ? mul2(bs, c) : fma2(bs, c, r[l2]);
            }
        }

        // quantize/dequantize, scalar on register halves (FRND on cvt pipe)
        float m[8];
        #pragma unroll
        for (int b = 0; b < 4; ++b) {
            float s0 = lo2(r[b]);
            float s1 = hi2(r[b]);
            m[2*b]   = rintf(s0 * (1.0f / QMc[i][2*b]))   * QMc[i][2*b];
            m[2*b+1] = rintf(s1 * (1.0f / QMc[i][2*b+1])) * QMc[i][2*b+1];
        }

        // row inv: P[c] = sum_j m[j] * D[j][c], packed over c-pairs
        #pragma unroll
        for (int j = 0; j < 8; ++j) {
            u64 bs = pk(m[j], m[j]);
            #pragma unroll
            for (int c2 = 0; c2 < 4; ++c2) {
                u64 c = pk(DMc[j][2*c2], DMc[j][2*c2+1]);
                A[i][c2] = (j == 0) ? mul2(bs, c) : fma2(bs, c, A[i][c2]);
            }
        }
    }

    // ---- pass 5: out = D^T @ P (column transform), streaming output rows --
    #pragma unroll
    for (int i = 0; i < 8; ++i) {
        u64 r0, r1, r2, r3;
        {
            u64 c = pk(DMc[0][i], DMc[0][i]);
            r0 = mul2(c, A[0][0]); r1 = mul2(c, A[0][1]);
            r2 = mul2(c, A[0][2]); r3 = mul2(c, A[0][3]);
        }
        #pragma unroll
        for (int k = 1; k < 8; ++k) {
            u64 c = pk(DMc[k][i], DMc[k][i]);
            r0 = fma2(c, A[k][0], r0); r1 = fma2(c, A[k][1], r1);
            r2 = fma2(c, A[k][2], r2); r3 = fma2(c, A[k][3], r3);
        }
        ulonglong2* op = reinterpret_cast<ulonglong2*>(q + (size_t)i * 512);
        op[0] = make_ulonglong2(r0, r1);
        op[1] = make_ulonglong2(r2, r3);
    }
}

extern "C" void kernel_launch(void* const* d_in, const int* in_sizes, int n_in,
                              void* d_out, int out_size)
{
    const float* in  = (const float*)d_in[0];
    float*       out = (float*)d_out;
    int nblk = in_sizes[0] / 64;                 // number of 8x8 blocks
    int grid = (nblk + 255) / 256;
    diffjpeg_kernel<<<grid, 256>>>(in, out, nblk);
}

// round 4
// speedup vs baseline: 1.3244x; 1.0440x over previous
#include <cuda_runtime.h>
#include <cuda_bf16.h>

// DiffJPEG per-8x8-block: D @ X @ D^T -> round(./Q)*Q -> D^T @ M @ D
// One thread per block. f32x2 packed math + even/odd butterfly decomposition:
// D[i][7-j] = +D[i][j] (even i) / -D[i][j] (odd i), so each 8-pt transform is
// 8 add/sub + two 4x4 matmuls. Row passes fuse even/odd into one packed lane.

using u64 = unsigned long long;

// D[i][j] = c_i * cos((2j+1) i pi / 16), c_0 = sqrt(1/8), else 0.5
__device__ constexpr float DMc[8][8] = {
    { 0.3535533905932738f,  0.3535533905932738f,  0.3535533905932738f,  0.3535533905932738f,
      0.3535533905932738f,  0.3535533905932738f,  0.3535533905932738f,  0.3535533905932738f },
    { 0.4903926402016152f,  0.4157348061512726f,  0.2777851165098011f,  0.0975451610080642f,
     -0.0975451610080642f, -0.2777851165098011f, -0.4157348061512726f, -0.4903926402016152f },
    { 0.4619397662556434f,  0.1913417161825449f, -0.1913417161825449f, -0.4619397662556434f,
     -0.4619397662556434f, -0.1913417161825449f,  0.1913417161825449f,  0.4619397662556434f },
    { 0.4157348061512726f, -0.0975451610080642f, -0.4903926402016152f, -0.2777851165098011f,
      0.2777851165098011f,  0.4903926402016152f,  0.0975451610080642f, -0.4157348061512726f },
    { 0.3535533905932738f, -0.3535533905932738f, -0.3535533905932738f,  0.3535533905932738f,
      0.3535533905932738f, -0.3535533905932738f, -0.3535533905932738f,  0.3535533905932738f },
    { 0.2777851165098011f, -0.4903926402016152f,  0.0975451610080642f,  0.4157348061512726f,
     -0.4157348061512726f, -0.0975451610080642f,  0.4903926402016152f, -0.2777851165098011f },
    { 0.1913417161825449f, -0.4619397662556434f,  0.4619397662556434f, -0.1913417161825449f,
     -0.1913417161825449f,  0.4619397662556434f, -0.4619397662556434f,  0.1913417161825449f },
    { 0.0975451610080642f, -0.2777851165098011f,  0.4157348061512726f, -0.4903926402016152f,
      0.4903926402016152f, -0.4157348061512726f,  0.2777851165098011f, -0.0975451610080642f },
};

// quality=50 -> Q == q_luma exactly.
__device__ constexpr float QMc[8][8] = {
    { 16.f, 11.f, 10.f, 16.f,  24.f,  40.f,  51.f,  61.f },
    { 12.f, 12.f, 14.f, 19.f,  26.f,  58.f,  60.f,  55.f },
    { 14.f, 13.f, 16.f, 24.f,  40.f,  57.f,  69.f,  56.f },
    { 14.f, 17.f, 22.f, 29.f,  51.f,  87.f,  80.f,  62.f },
    { 18.f, 22.f, 37.f, 56.f,  68.f, 109.f, 103.f,  77.f },
    { 24.f, 35.f, 55.f, 64.f,  81.f, 104.f, 113.f,  92.f },
    { 49.f, 64.f, 78.f, 87.f, 103.f, 121.f, 120.f, 101.f },
    { 72.f, 92.f, 95.f, 98.f, 112.f, 100.f, 103.f,  99.f },
};

__device__ __forceinline__ u64 pk(float a, float b) {
    u64 r; asm("mov.b64 %0, {%1, %2};" : "=l"(r) : "f"(a), "f"(b)); return r;
}
__device__ __forceinline__ void unpk(float& a, float& b, u64 v) {
    asm("mov.b64 {%0, %1}, %2;" : "=f"(a), "=f"(b) : "l"(v));
}
__device__ __forceinline__ u64 fma2(u64 a, u64 b, u64 c) {
    u64 d; asm("fma.rn.f32x2 %0, %1, %2, %3;" : "=l"(d) : "l"(a), "l"(b), "l"(c)); return d;
}
__device__ __forceinline__ u64 mul2(u64 a, u64 b) {
    u64 d; asm("mul.rn.f32x2 %0, %1, %2;" : "=l"(d) : "l"(a), "l"(b)); return d;
}
__device__ __forceinline__ u64 add2(u64 a, u64 b) {
    u64 d; asm("add.rn.f32x2 %0, %1, %2;" : "=l"(d) : "l"(a), "l"(b)); return d;
}
// a - b  (via fma with packed -1; guaranteed-valid encoding)
__device__ __forceinline__ u64 sub2(u64 a, u64 b, u64 neg1) {
    return fma2(b, neg1, a);
}

__global__ void __launch_bounds__(256, 2)
diffjpeg_kernel(const float* __restrict__ in, float* __restrict__ out, int nblk)
{
    int tid = blockIdx.x * 256 + threadIdx.x;
    if (tid >= nblk) return;

    const u64 NEG1 = pk(-1.0f, -1.0f);

    int bw  = tid & 63;           // block col (64 per row)
    int t1  = tid >> 6;
    int bh  = t1 & 63;            // block row
    int img = t1 >> 6;            // fused (B,C) plane

    size_t base = ((size_t)img << 18) + ((size_t)bh << 12) + ((size_t)bw << 3);
    const float* p = in  + base;
    float*       q = out + base;

    u64 A[8][4];   // 8 rows x 4 packed j-pairs

    // ---- pass 1: A = D @ X (column transform) via row butterfly ----------
    {
        u64 S[4][4], Dd[4][4];     // S[t] = row t + row 7-t ; Dd[t] = diff
        #pragma unroll
        for (int t = 0; t < 4; ++t) {
            const ulonglong2* rt = reinterpret_cast<const ulonglong2*>(p + (size_t)t * 512);
            const ulonglong2* rb = reinterpret_cast<const ulonglong2*>(p + (size_t)(7 - t) * 512);
            ulonglong2 ta = rt[0], tb = rt[1];
            ulonglong2 ba = rb[0], bb = rb[1];
            u64 xt[4] = { ta.x, ta.y, tb.x, tb.y };
            u64 xb[4] = { ba.x, ba.y, bb.x, bb.y };
            #pragma unroll
            for (int pp = 0; pp < 4; ++pp) {
                S[t][pp]  = add2(xt[pp], xb[pp]);
                Dd[t][pp] = sub2(xt[pp], xb[pp], NEG1);
            }
        }
        // even output rows from S, odd from Dd
        #pragma unroll
        for (int u = 0; u < 4; ++u) {
            #pragma unroll
            for (int pp = 0; pp < 4; ++pp) {
                u64 acc = mul2(pk(DMc[2*u][0], DMc[2*u][0]), S[0][pp]);
                #pragma unroll
                for (int t = 1; t < 4; ++t)
                    acc = fma2(pk(DMc[2*u][t], DMc[2*u][t]), S[t][pp], acc);
                A[2*u][pp] = acc;
            }
        }
        #pragma unroll
        for (int u = 0; u < 4; ++u) {
            #pragma unroll
            for (int pp = 0; pp < 4; ++pp) {
                u64 acc = mul2(pk(DMc[2*u+1][0], DMc[2*u+1][0]), Dd[0][pp]);
                #pragma unroll
                for (int t = 1; t < 4; ++t)
                    acc = fma2(pk(DMc[2*u+1][t], DMc[2*u+1][t]), Dd[t][pp], acc);
                A[2*u+1][pp] = acc;
            }
        }
    }

    // ---- per row i: row-fwd butterfly, quantize, row-inv butterfly --------
    #pragma unroll
    for (int i = 0; i < 8; ++i) {
        float a0,a1,a2,a3,a4,a5,a6,a7;
        unpk(a0, a1, A[i][0]); unpk(a2, a3, A[i][1]);
        unpk(a4, a5, A[i][2]); unpk(a6, a7, A[i][3]);

        // sd[j] = (a[j]+a[7-j], a[j]-a[7-j])  -- scalar adds, pack free-ish
        u64 sd[4];
        sd[0] = pk(a0 + a7, a0 - a7);
        sd[1] = pk(a1 + a6, a1 - a6);
        sd[2] = pk(a2 + a5, a2 - a5);
        sd[3] = pk(a3 + a4, a3 - a4);

        // r[t] = (dct[2t], dct[2t+1]) = sum_j sd[j] * (D[2t][j], D[2t+1][j])
        u64 r[4];
        #pragma unroll
        for (int t = 0; t < 4; ++t) {
            u64 acc = mul2(sd[0], pk(DMc[2*t][0], DMc[2*t+1][0]));
            #pragma unroll
            for (int j = 1; j < 4; ++j)
                acc = fma2(sd[j], pk(DMc[2*t][j], DMc[2*t+1][j]), acc);
            r[t] = acc;
        }

        // quantize/dequantize: packed scale, scalar rint, scalar rescale
        float m[8];
        #pragma unroll
        for (int t = 0; t < 4; ++t) {
            u64 sc = mul2(r[t], pk(1.0f / QMc[i][2*t], 1.0f / QMc[i][2*t+1]));
            float s0, s1; unpk(s0, s1, sc);
            m[2*t]   = rintf(s0) * QMc[i][2*t];
            m[2*t+1] = rintf(s1) * QMc[i][2*t+1];
        }

        // row-inv: u[c] = sum_t m[2t]*D[2t][c] ; v[c] = sum_t m[2t+1]*D[2t+1][c]
        // P[c] = u+v, P[7-c] = u-v   (c = 0..3)
        u64 U01, U23, V01, V23;
        {
            u64 be = pk(m[0], m[0]);
            U01 = mul2(be, pk(DMc[0][0], DMc[0][1]));
            U23 = mul2(be, pk(DMc[0][2], DMc[0][3]));
            u64 bo = pk(m[1], m[1]);
            V01 = mul2(bo, pk(DMc[1][0], DMc[1][1]));
            V23 = mul2(bo, pk(DMc[1][2], DMc[1][3]));
        }
        #pragma unroll
        for (int t = 1; t < 4; ++t) {
            u64 be = pk(m[2*t], m[2*t]);
            U01 = fma2(be, pk(DMc[2*t][0], DMc[2*t][1]), U01);
            U23 = fma2(be, pk(DMc[2*t][2], DMc[2*t][3]), U23);
            u64 bo = pk(m[2*t+1], m[2*t+1]);
            V01 = fma2(bo, pk(DMc[2*t+1][0], DMc[2*t+1][1]), V01);
            V23 = fma2(bo, pk(DMc[2*t+1][2], DMc[2*t+1][3]), V23);
        }
        A[i][0] = add2(U01, V01);            // (P0, P1)
        A[i][1] = add2(U23, V23);            // (P2, P3)
        u64 t76 = sub2(U01, V01, NEG1);      // (P7, P6)
        u64 t54 = sub2(U23, V23, NEG1);      // (P5, P4)
        { float x, y; unpk(x, y, t54); A[i][2] = pk(y, x); }  // (P4, P5)
        { float x, y; unpk(x, y, t76); A[i][3] = pk(y, x); }  // (P6, P7)
    }

    // ---- pass 5: out = D^T @ P (column transform) via butterfly ----------
    // out[i] = u_i + v_i, out[7-i] = u_i - v_i,
    //   u_i = sum_t D[2t][i]   * P[2t],  v_i = sum_t D[2t+1][i] * P[2t+1]
    #pragma unroll
    for (int i = 0; i < 4; ++i) {
        u64 u[4], v[4];
        {
            u64 ce = pk(DMc[0][i], DMc[0][i]);
            u64 co = pk(DMc[1][i], DMc[1][i]);
            #pragma unroll
            for (int pp = 0; pp < 4; ++pp) {
                u[pp] = mul2(ce, A[0][pp]);
                v[pp] = mul2(co, A[1][pp]);
            }
        }
        #pragma unroll
        for (int t = 1; t < 4; ++t) {
            u64 ce = pk(DMc[2*t][i], DMc[2*t][i]);
            u64 co = pk(DMc[2*t+1][i], DMc[2*t+1][i]);
            #pragma unroll
            for (int pp = 0; pp < 4; ++pp) {
                u[pp] = fma2(ce, A[2*t][pp], u[pp]);
                v[pp] = fma2(co, A[2*t+1][pp], v[pp]);
            }
        }
        ulonglong2* ot = reinterpret_cast<ulonglong2*>(q + (size_t)i * 512);
        ulonglong2* ob = reinterpret_cast<ulonglong2*>(q + (size_t)(7 - i) * 512);
        ot[0] = make_ulonglong2(add2(u[0], v[0]), add2(u[1], v[1]));
        ot[1] = make_ulonglong2(add2(u[2], v[2]), add2(u[3], v[3]));
        ob[0] = make_ulonglong2(sub2(u[0], v[0], NEG1), sub2(u[1], v[1], NEG1));
        ob[1] = make_ulonglong2(sub2(u[2], v[2], NEG1), sub2(u[3], v[3], NEG1));
    }
}

extern "C" void kernel_launch(void* const* d_in, const int* in_sizes, int n_in,
                              void* d_out, int out_size)
{
    const float* in  = (const float*)d_in[0];
    float*       out = (float*)d_out;
    int nblk = in_sizes[0] / 64;                 // number of 8x8 blocks
    int grid = (nblk + 255) / 256;
    diffjpeg_kernel<<<grid, 256>>>(in, out, nblk);
}